// round 14
// baseline (speedup 1.0000x reference)
#include <cuda_runtime.h>

#define K 19
#define L 2048
#define B 512
#define START_ID 17
#define PAD_ID 18
#define NEG -1000.0f
#define NSEG 16         // backtrack segments per row
#define CPL 10          // boundary chains per lane
#define FULL 0xffffffffu
#define ROWBYTES (L / 4 * 80)   // packed bp: [L/4 groups][20 lanes][4 bytes]

__device__ int g_elt4;
__device__ int g_len[B];
__device__ int g_ord[B];

__global__ void detect_kernel(const unsigned char* __restrict__ m) {
    __shared__ int found;
    if (threadIdx.x == 0) found = 0;
    __syncthreads();
    int f = 0;
    for (int i = threadIdx.x * 4 + 1; i < 65536; i += blockDim.x * 4)
        f |= m[i];
    if (f) found = 1;
    __syncthreads();
    if (threadIdx.x == 0) g_elt4 = found ? 0 : 1;
}

// one warp per row: count mask nonzeros
__global__ void length_kernel(const unsigned char* __restrict__ mask) {
    const int wid = threadIdx.x >> 5, lane = threadIdx.x & 31;
    const int row = blockIdx.x * 4 + wid;
    int len = 0;
    if (g_elt4) {
        const unsigned* m = (const unsigned*)mask + (size_t)row * L;
        for (int i = lane; i < L; i += 32) len += (m[i] != 0u);
    } else {
        const unsigned char* m = mask + (size_t)row * L;
        for (int i = lane; i < L; i += 32) len += (m[i] != 0);
    }
#pragma unroll
    for (int o = 16; o; o >>= 1) len += __shfl_xor_sync(FULL, len, o);
    if (lane == 0) g_len[row] = len;
}

// bitonic sort 512 keys; g_ord = row indices in DESCENDING length order
__global__ void sort_kernel() {
    __shared__ unsigned key[B];
    const int i = threadIdx.x;
    key[i] = ((unsigned)g_len[i] << 9) | (unsigned)(511 - i);
    for (int k = 2; k <= B; k <<= 1)
        for (int j2 = k >> 1; j2 > 0; j2 >>= 1) {
            __syncthreads();
            const int p = i ^ j2;
            if (p > i) {
                unsigned a = key[i], c = key[p];
                const bool up = ((i & k) == 0);
                if ((a > c) == up) { key[i] = c; key[p] = a; }
            }
        }
    __syncthreads();
    g_ord[i] = 511 - (int)(key[B - 1 - i] & 511u);
}

// bp(t, c) packed-4 layout
__device__ __forceinline__ int BPGET(const unsigned char* bp, int t, int c) {
    return bp[((t >> 2) * 80) + (c << 2) + (t & 3)];
}

__device__ __forceinline__ unsigned smem_u32(const void* p) {
    unsigned a;
    asm("{ .reg .u64 t; cvta.to.shared.u64 t, %1; cvt.u32.u64 %0, t; }"
        : "=r"(a) : "l"(p));
    return a;
}

// fused (value,index) tournament node; strict '>' + lower-index LO side
// at every node = exact first-occurrence argmax.
#define NODE(VO, IO, LOV, LOI, HIV, HII)                                   \
    asm("{ .reg .pred p;\n\t"                                              \
        "setp.gt.f32 p, %3, %2;\n\t"                                       \
        "selp.f32 %0, %3, %2, p;\n\t"                                      \
        "selp.b32 %1, %5, %4, p; }"                                        \
        : "=f"(VO), "=r"(IO)                                               \
        : "f"(LOV), "f"(HIV), "r"(LOI), "r"(HII));

#define LOADQ(S, SRC)                                                      \
    asm volatile("ld.shared.v4.f32 {%0,%1,%2,%3}, [%4];"                   \
        : "=f"(S[0]), "=f"(S[1]), "=f"(S[2]), "=f"(S[3])                   \
        : "r"(SRC) : "memory");                                            \
    asm volatile("ld.shared.v4.f32 {%0,%1,%2,%3}, [%4];"                   \
        : "=f"(S[4]), "=f"(S[5]), "=f"(S[6]), "=f"(S[7])                   \
        : "r"((SRC) + 16) : "memory");                                     \
    asm volatile("ld.shared.v4.f32 {%0,%1,%2,%3}, [%4];"                   \
        : "=f"(S[8]), "=f"(S[9]), "=f"(S[10]), "=f"(S[11])                 \
        : "r"((SRC) + 32) : "memory");                                     \
    asm volatile("ld.shared.v4.f32 {%0,%1,%2,%3}, [%4];"                   \
        : "=f"(S[12]), "=f"(S[13]), "=f"(S[14]), "=f"(S[15])               \
        : "r"((SRC) + 48) : "memory");                                     \
    asm volatile("ld.shared.v4.f32 {%0,%1,%2,%3}, [%4];"                   \
        : "=f"(S[16]), "=f"(S[17]), "=f"(S[18]), "=f"(S[19])               \
        : "r"((SRC) + 64) : "memory");

#define COMPUTE(S, ND, EMIT, ARG) {                                        \
    S[0]+=Trow[0];   S[1]+=Trow[1];   S[2]+=Trow[2];   S[3]+=Trow[3];      \
    S[4]+=Trow[4];   S[5]+=Trow[5];   S[6]+=Trow[6];   S[7]+=Trow[7];      \
    S[8]+=Trow[8];   S[9]+=Trow[9];   S[10]+=Trow[10]; S[11]+=Trow[11];    \
    S[12]+=Trow[12]; S[13]+=Trow[13]; S[14]+=Trow[14]; S[15]+=Trow[15];    \
    S[16]+=Trow[16]; S[17]+=Trow[17]; S[18]+=Trow[18];                     \
    float a0,a1,a2,a3,a4,a5,a6,a7,a8; int p0,p1,p2,p3,p4,p5,p6,p7,p8;      \
    NODE(a0,p0, S[0],0,   S[1],1)                                          \
    NODE(a1,p1, S[2],2,   S[3],3)                                          \
    NODE(a2,p2, S[4],4,   S[5],5)                                          \
    NODE(a3,p3, S[6],6,   S[7],7)                                          \
    NODE(a4,p4, S[8],8,   S[9],9)                                          \
    NODE(a5,p5, S[10],10, S[11],11)                                        \
    NODE(a6,p6, S[12],12, S[13],13)                                        \
    NODE(a7,p7, S[14],14, S[15],15)                                        \
    NODE(a8,p8, S[16],16, S[17],17)                                        \
    float b0,b1,b2,b3,b4; int q0,q1,q2,q3,q4;                              \
    NODE(b0,q0, a0,p0, a1,p1)                                              \
    NODE(b1,q1, a2,p2, a3,p3)                                              \
    NODE(b2,q2, a4,p4, a5,p5)                                              \
    NODE(b3,q3, a6,p6, a7,p7)                                              \
    NODE(b4,q4, a8,p8, S[18],18)                                           \
    float c0,c1; int r0_,r1_;                                              \
    NODE(c0,r0_, b0,q0, b1,q1)                                             \
    NODE(c1,r1_, b2,q2, b3,q3)                                             \
    float dd; int rr_;                                                     \
    NODE(dd,rr_, c0,r0_, c1,r1_)                                           \
    float bv; NODE(bv,ARG, dd,rr_, b4,q4)                                  \
    ND = bv + (EMIT);                                                      \
}

#define STORE(SVAR, ND) {                                                  \
    unsigned d_ = (SVAR) ^ 128u;                                           \
    asm volatile("st.shared.f32 [%0], %1;"                                 \
        :: "r"(d_ + laneoff), "f"(ND) : "memory");                         \
    SVAR = d_;                                                             \
}

#define PACK(W0, ARG, PH, BPW) {                                           \
    if ((PH) == 0) W0 = (unsigned)(ARG);                                   \
    else           W0 |= (unsigned)(ARG) << (8 * (PH));                    \
    if ((PH) == 3) { if (lane < K) *BPW = W0; BPW += 20; }                 \
}

#define STEPA(PH, EMIT) { float s_[20]; int a_;                            \
    LOADQ(s_, sA) COMPUTE(s_, ndA, EMIT, a_)                               \
    STORE(sA, ndA) PACK(w0A, a_, PH, bpwA) }

#define STEPB(PH, EMIT) { float s_[20]; int a_;                            \
    LOADQ(s_, sB) COMPUTE(s_, ndB, EMIT, a_)                               \
    STORE(sB, ndB) PACK(w0B, a_, PH, bpwB) }

// fused pair step: both rows' loads issue before either store (keeps the
// two chains overlapped despite asm memory-clobber ordering)
#define STEP2(PH, EA, EB) { float sa_[20], sb_[20]; int aA_, aB_;          \
    LOADQ(sa_, sA) LOADQ(sb_, sB)                                          \
    COMPUTE(sa_, ndA, EA, aA_) STORE(sA, ndA)                              \
    COMPUTE(sb_, ndB, EB, aB_) STORE(sB, ndB)                              \
    PACK(w0A, aA_, PH, bpwA) PACK(w0B, aB_, PH, bpwB) }

__global__ void __launch_bounds__(64, 1) viterbi_kernel(
    const float* __restrict__ P,          // [B, L, K]
    const float* __restrict__ Tm,         // [K, K]
    float* __restrict__ out)              // [B, L] float32
{
    extern __shared__ unsigned char dsm[];            // 4 * ROWBYTES
    __shared__ __align__(256) float dpbuf[2][2][2][32];
    __shared__ unsigned char fmap[2][2][NSEG][K];
    __shared__ unsigned char eseg[2][2][NSEG];

    const int wid  = threadIdx.x >> 5;
    const int lane = threadIdx.x & 31;
    const int j    = (lane < K) ? lane : 0;
    const unsigned laneoff = (unsigned)lane << 2;

    const int ww   = blockIdx.x * 2 + wid;
    const int rowA = g_ord[2 * ww];       // longer row
    const int rowB = g_ord[2 * ww + 1];   // shorter (sorted desc)
    const int lenA = g_len[rowA];
    const int lenB = g_len[rowB];

    unsigned char* __restrict__ bpA = dsm + (wid * 2 + 0) * ROWBYTES;
    unsigned char* __restrict__ bpB = dsm + (wid * 2 + 1) * ROWBYTES;

    float Trow[K];
#pragma unroll
    for (int k = 0; k < K; ++k) Trow[k] = Tm[j * K + k];

    const float* PbA = P + (size_t)rowA * L * K;
    const float* PbB = P + (size_t)rowB * L * K;

    dpbuf[wid][0][0][lane] = (lane == START_ID) ? 0.0f : NEG;
    dpbuf[wid][0][1][lane] = NEG;
    dpbuf[wid][1][0][lane] = (lane == START_ID) ? 0.0f : NEG;
    dpbuf[wid][1][1][lane] = NEG;
    __syncwarp();

    unsigned sA = smem_u32(&dpbuf[wid][0][0][0]);
    unsigned sB = smem_u32(&dpbuf[wid][1][0][0]);

    float ndA = (j == START_ID && lane < K) ? 0.0f : NEG;
    float ndB = ndA;
    unsigned* bpwA = (unsigned*)bpA + lane;
    unsigned* bpwB = (unsigned*)bpB + lane;
    unsigned w0A = 0, w0B = 0;

    // emission prefetch, depth 4 per row (clamped init)
    float eA0 = __ldg(PbA + j + (size_t)min(0, lenA - 1) * K);
    float eA1 = __ldg(PbA + j + (size_t)min(1, lenA - 1) * K);
    float eA2 = __ldg(PbA + j + (size_t)min(2, lenA - 1) * K);
    float eA3 = __ldg(PbA + j + (size_t)min(3, lenA - 1) * K);
    float eB0 = __ldg(PbB + j + (size_t)min(0, lenB - 1) * K);
    float eB1 = __ldg(PbB + j + (size_t)min(1, lenB - 1) * K);
    float eB2 = __ldg(PbB + j + (size_t)min(2, lenB - 1) * K);
    float eB3 = __ldg(PbB + j + (size_t)min(3, lenB - 1) * K);

    int t = 0;
    // ---- phase 1: interleaved full-speed groups (unguarded prefetch) ----
    {
        const float* epA = PbA + j + (size_t)4 * K;
        const float* epB = PbB + j + (size_t)4 * K;
        for (; t + 8 <= lenB; t += 4) {
            STEP2(0, eA0, eB0); eA0 = __ldg(epA + 0 * K); eB0 = __ldg(epB + 0 * K);
            STEP2(1, eA1, eB1); eA1 = __ldg(epA + 1 * K); eB1 = __ldg(epB + 1 * K);
            STEP2(2, eA2, eB2); eA2 = __ldg(epA + 2 * K); eB2 = __ldg(epB + 2 * K);
            STEP2(3, eA3, eB3); eA3 = __ldg(epA + 3 * K); eB3 = __ldg(epB + 3 * K);
            epA += 4 * K; epB += 4 * K;
        }
    }
    // ---- phase 1b: one clamped interleaved group if >= 4 B-steps left ----
    if (t + 4 <= lenB) {
        STEP2(0, eA0, eB0);
        eA0 = __ldg(PbA + j + (size_t)min(t + 4, lenA - 1) * K);
        eB0 = __ldg(PbB + j + (size_t)min(t + 4, lenB - 1) * K);
        STEP2(1, eA1, eB1);
        eA1 = __ldg(PbA + j + (size_t)min(t + 5, lenA - 1) * K);
        eB1 = __ldg(PbB + j + (size_t)min(t + 5, lenB - 1) * K);
        STEP2(2, eA2, eB2);
        eA2 = __ldg(PbA + j + (size_t)min(t + 6, lenA - 1) * K);
        eB2 = __ldg(PbB + j + (size_t)min(t + 6, lenB - 1) * K);
        STEP2(3, eA3, eB3);
        eA3 = __ldg(PbA + j + (size_t)min(t + 7, lenA - 1) * K);
        eB3 = __ldg(PbB + j + (size_t)min(t + 7, lenB - 1) * K);
        t += 4;
    }
    // ---- phase 1c: partial group, rB in [0,3], rA4 = min(lenA - t, 4) ----
    {
        const int rB = lenB - t;
        const int rA4 = min(lenA - t, 4);
        if (rA4 > 0) STEPA(0, eA0);
        if (rB  > 0) STEPB(0, eB0);
        if (rA4 > 1) STEPA(1, eA1);
        if (rB  > 1) STEPB(1, eB1);
        if (rA4 > 2) STEPA(2, eA2);
        if (rB  > 2) STEPB(2, eB2);
        if (rA4 > 3) STEPA(3, eA3);
        if (rB > 0 && rB < 4 && lane < K) *bpwB = w0B;      // B partial word
        if (rA4 > 0 && rA4 < 4 && lane < K) *bpwA = w0A;    // A done, partial
        t += rA4;
    }
    // ---- phase 2: A-only full-speed groups ----
    if (t + 8 <= lenA) {
        eA0 = __ldg(PbA + j + (size_t)(t + 0) * K);
        eA1 = __ldg(PbA + j + (size_t)(t + 1) * K);
        eA2 = __ldg(PbA + j + (size_t)(t + 2) * K);
        eA3 = __ldg(PbA + j + (size_t)(t + 3) * K);
        const float* epA = PbA + j + (size_t)(t + 4) * K;
        for (; t + 8 <= lenA; t += 4) {
            STEPA(0, eA0); eA0 = __ldg(epA + 0 * K);
            STEPA(1, eA1); eA1 = __ldg(epA + 1 * K);
            STEPA(2, eA2); eA2 = __ldg(epA + 2 * K);
            STEPA(3, eA3); eA3 = __ldg(epA + 3 * K);
            epA += 4 * K;
        }
    }
    // ---- phase 2 tail: r in [0,7] ----
    {
        const int r = lenA - t;
        if (r > 0) {
            eA0 = __ldg(PbA + j + (size_t)min(t + 0, lenA - 1) * K);
            eA1 = __ldg(PbA + j + (size_t)min(t + 1, lenA - 1) * K);
            eA2 = __ldg(PbA + j + (size_t)min(t + 2, lenA - 1) * K);
            eA3 = __ldg(PbA + j + (size_t)min(t + 3, lenA - 1) * K);
            STEPA(0, eA0);
            if (r > 1) STEPA(1, eA1);
            if (r > 2) STEPA(2, eA2);
            if (r > 3) STEPA(3, eA3);
            if (r > 4) { float ex = __ldg(PbA + j + (size_t)(t + 4) * K);
                         STEPA(0, ex); }
            if (r > 5) { float ex = __ldg(PbA + j + (size_t)(t + 5) * K);
                         STEPA(1, ex); }
            if (r > 6) { float ex = __ldg(PbA + j + (size_t)(t + 6) * K);
                         STEPA(2, ex); }
            if ((r & 3) != 0 && lane < K) *bpwA = w0A;
        }
    }
    __syncwarp();

    // ================= backtrack + output, per row =================
    for (int rsel = 0; rsel < 2; ++rsel) {
        const int brow = rsel ? rowB : rowA;
        const int blen = rsel ? lenB : lenA;
        const float bnd = rsel ? ndB : ndA;
        const unsigned char* __restrict__ bp = rsel ? bpB : bpA;

        // final transition into PAD, first-occurrence argmax
        const float fv = (lane < K) ? (bnd + Tm[PAD_ID * K + j]) : NEG;
        int last = 0;
        {
            float bestf = __shfl_sync(FULL, fv, 0);
#pragma unroll
            for (int k = 1; k < K; ++k) {
                const float vk = __shfl_sync(FULL, fv, k);
                if (vk > bestf) { bestf = vk; last = k; }
            }
        }

        float* ob = out + (size_t)brow * L;
        for (int tt = blen + lane; tt < L; tt += 32) ob[tt] = -1.0f;

        const int segw = (blen + NSEG - 1) / NSEG;
        const int nseg = (blen + segw - 1) / segw;

        int cur[CPL], tq[CPL], t0q[CPL];
#pragma unroll
        for (int q = 0; q < CPL; ++q) {
            const int cid = lane + 32 * q;
            if (cid < nseg * K) {
                const int i = cid / K, e = cid - i * K;
                const int t0 = i * segw;
                const int t1 = min(t0 + segw, blen);
                cur[q] = e; tq[q] = t1 - 1; t0q[q] = t0;
            } else { cur[q] = 0; tq[q] = 0; t0q[q] = 0; }
        }
        for (int p = 0; p < segw - 1; ++p) {
#pragma unroll
            for (int q = 0; q < CPL; ++q)
                if (tq[q] > t0q[q]) {
                    cur[q] = BPGET(bp, tq[q], cur[q]);
                    tq[q]--;
                }
        }
#pragma unroll
        for (int q = 0; q < CPL; ++q) {
            const int cid = lane + 32 * q;
            if (cid < nseg * K) {
                const int i = cid / K, e = cid - i * K;
                fmap[wid][rsel][i][e] = (unsigned char)cur[q];
            }
        }
        __syncwarp();

        if (lane == 0) {
            int e = last;
            eseg[wid][rsel][nseg - 1] = (unsigned char)e;
            for (int i = nseg - 1; i > 0; --i) {
                const int t0 = i * segw;
                const int pc = fmap[wid][rsel][i][e];
                e = BPGET(bp, t0, pc);
                eseg[wid][rsel][i - 1] = (unsigned char)e;
            }
        }
        __syncwarp();

        if (lane < nseg) {
            const int t0 = lane * segw;
            const int t1 = min(t0 + segw, blen);
            int c = eseg[wid][rsel][lane];
            ob[t1 - 1] = (float)c;
            for (int tt = t1 - 2; tt >= t0; --tt) {
                c = BPGET(bp, tt + 1, c);
                ob[tt] = (float)c;
            }
        }
        __syncwarp();
    }
}

extern "C" void kernel_launch(void* const* d_in, const int* in_sizes, int n_in,
                              void* d_out, int out_size) {
    const float* P = (const float*)d_in[0];
    const float* T = (const float*)d_in[1];
    const unsigned char* mask = (const unsigned char*)d_in[2];
    float* out = (float*)d_out;

    const int smem = 4 * ROWBYTES;  // 163840 B
    cudaFuncSetAttribute(viterbi_kernel,
                         cudaFuncAttributeMaxDynamicSharedMemorySize, smem);

    detect_kernel<<<1, 256>>>(mask);
    length_kernel<<<128, 128>>>(mask);
    sort_kernel<<<1, 512>>>();
    viterbi_kernel<<<B / 4, 64, smem>>>(P, T, out);
}

// round 15
// speedup vs baseline: 1.0765x; 1.0765x over previous
#include <cuda_runtime.h>

#define K 19
#define L 2048
#define B 512
#define START_ID 17
#define PAD_ID 18
#define NEG -1000.0f
#define NSEG 16
#define CPL 10
#define FULL 0xffffffffu
#define ROWBYTES (L / 4 * 80)   // packed bp: [L/4 groups][20 lanes][4 bytes]

__device__ int g_elt4;
__device__ int g_len[B];
__device__ int g_ord[B];

__global__ void detect_kernel(const unsigned char* __restrict__ m) {
    __shared__ int found;
    if (threadIdx.x == 0) found = 0;
    __syncthreads();
    int f = 0;
    for (int i = threadIdx.x * 4 + 1; i < 65536; i += blockDim.x * 4)
        f |= m[i];
    if (f) found = 1;
    __syncthreads();
    if (threadIdx.x == 0) g_elt4 = found ? 0 : 1;
}

__global__ void length_kernel(const unsigned char* __restrict__ mask) {
    const int wid = threadIdx.x >> 5, lane = threadIdx.x & 31;
    const int row = blockIdx.x * 4 + wid;
    int len = 0;
    if (g_elt4) {
        const unsigned* m = (const unsigned*)mask + (size_t)row * L;
        for (int i = lane; i < L; i += 32) len += (m[i] != 0u);
    } else {
        const unsigned char* m = mask + (size_t)row * L;
        for (int i = lane; i < L; i += 32) len += (m[i] != 0);
    }
#pragma unroll
    for (int o = 16; o; o >>= 1) len += __shfl_xor_sync(FULL, len, o);
    if (lane == 0) g_len[row] = len;
}

// bitonic sort; g_ord = row indices in DESCENDING length order
__global__ void sort_kernel() {
    __shared__ unsigned key[B];
    const int i = threadIdx.x;
    key[i] = ((unsigned)g_len[i] << 9) | (unsigned)(511 - i);
    for (int k = 2; k <= B; k <<= 1)
        for (int j2 = k >> 1; j2 > 0; j2 >>= 1) {
            __syncthreads();
            const int p = i ^ j2;
            if (p > i) {
                unsigned a = key[i], c = key[p];
                const bool up = ((i & k) == 0);
                if ((a > c) == up) { key[i] = c; key[p] = a; }
            }
        }
    __syncthreads();
    g_ord[i] = 511 - (int)(key[B - 1 - i] & 511u);
}

__device__ __forceinline__ int BPGET(const unsigned char* bp, int t, int c) {
    return bp[((t >> 2) * 80) + (c << 2) + (t & 3)];
}

__device__ __forceinline__ unsigned smem_u32(const void* p) {
    unsigned a;
    asm("{ .reg .u64 t; cvta.to.shared.u64 t, %1; cvt.u32.u64 %0, t; }"
        : "=r"(a) : "l"(p));
    return a;
}

#define NODE(VO, IO, LOV, LOI, HIV, HII)                                   \
    asm("{ .reg .pred p;\n\t"                                              \
        "setp.gt.f32 p, %3, %2;\n\t"                                       \
        "selp.f32 %0, %3, %2, p;\n\t"                                      \
        "selp.b32 %1, %5, %4, p; }"                                        \
        : "=f"(VO), "=r"(IO)                                               \
        : "f"(LOV), "f"(HIV), "r"(LOI), "r"(HII));

#define LOADQ(S, SRC)                                                      \
    asm volatile("ld.shared.v4.f32 {%0,%1,%2,%3}, [%4];"                   \
        : "=f"(S[0]), "=f"(S[1]), "=f"(S[2]), "=f"(S[3])                   \
        : "r"(SRC) : "memory");                                            \
    asm volatile("ld.shared.v4.f32 {%0,%1,%2,%3}, [%4];"                   \
        : "=f"(S[4]), "=f"(S[5]), "=f"(S[6]), "=f"(S[7])                   \
        : "r"((SRC) + 16) : "memory");                                     \
    asm volatile("ld.shared.v4.f32 {%0,%1,%2,%3}, [%4];"                   \
        : "=f"(S[8]), "=f"(S[9]), "=f"(S[10]), "=f"(S[11])                 \
        : "r"((SRC) + 32) : "memory");                                     \
    asm volatile("ld.shared.v4.f32 {%0,%1,%2,%3}, [%4];"                   \
        : "=f"(S[12]), "=f"(S[13]), "=f"(S[14]), "=f"(S[15])               \
        : "r"((SRC) + 48) : "memory");                                     \
    asm volatile("ld.shared.v4.f32 {%0,%1,%2,%3}, [%4];"                   \
        : "=f"(S[16]), "=f"(S[17]), "=f"(S[18]), "=f"(S[19])               \
        : "r"((SRC) + 64) : "memory");

#define COMPUTE(S, ND, EMIT, ARG) {                                        \
    S[0]+=Trow[0];   S[1]+=Trow[1];   S[2]+=Trow[2];   S[3]+=Trow[3];      \
    S[4]+=Trow[4];   S[5]+=Trow[5];   S[6]+=Trow[6];   S[7]+=Trow[7];      \
    S[8]+=Trow[8];   S[9]+=Trow[9];   S[10]+=Trow[10]; S[11]+=Trow[11];    \
    S[12]+=Trow[12]; S[13]+=Trow[13]; S[14]+=Trow[14]; S[15]+=Trow[15];    \
    S[16]+=Trow[16]; S[17]+=Trow[17]; S[18]+=Trow[18];                     \
    float a0,a1,a2,a3,a4,a5,a6,a7,a8; int p0,p1,p2,p3,p4,p5,p6,p7,p8;      \
    NODE(a0,p0, S[0],0,   S[1],1)                                          \
    NODE(a1,p1, S[2],2,   S[3],3)                                          \
    NODE(a2,p2, S[4],4,   S[5],5)                                          \
    NODE(a3,p3, S[6],6,   S[7],7)                                          \
    NODE(a4,p4, S[8],8,   S[9],9)                                          \
    NODE(a5,p5, S[10],10, S[11],11)                                        \
    NODE(a6,p6, S[12],12, S[13],13)                                        \
    NODE(a7,p7, S[14],14, S[15],15)                                        \
    NODE(a8,p8, S[16],16, S[17],17)                                        \
    float b0,b1,b2,b3,b4; int q0,q1,q2,q3,q4;                              \
    NODE(b0,q0, a0,p0, a1,p1)                                              \
    NODE(b1,q1, a2,p2, a3,p3)                                              \
    NODE(b2,q2, a4,p4, a5,p5)                                              \
    NODE(b3,q3, a6,p6, a7,p7)                                              \
    NODE(b4,q4, a8,p8, S[18],18)                                           \
    float c0,c1; int r0_,r1_;                                              \
    NODE(c0,r0_, b0,q0, b1,q1)                                             \
    NODE(c1,r1_, b2,q2, b3,q3)                                             \
    float dd; int rr_;                                                     \
    NODE(dd,rr_, c0,r0_, c1,r1_)                                           \
    float bv; NODE(bv,ARG, dd,rr_, b4,q4)                                  \
    ND = bv + (EMIT);                                                      \
}

#define STORE(SVAR, ND) {                                                  \
    unsigned d_ = (SVAR) ^ 128u;                                           \
    asm volatile("st.shared.f32 [%0], %1;"                                 \
        :: "r"(d_ + laneoff), "f"(ND) : "memory");                         \
    SVAR = d_;                                                             \
}

#define PACK(W0, ARG, PH, BPW) {                                           \
    if ((PH) == 0) W0 = (unsigned)(ARG);                                   \
    else           W0 |= (unsigned)(ARG) << (8 * (PH));                    \
    if ((PH) == 3) { if (lane < K) *BPW = W0; BPW += 20; }                 \
}

// compute+store+pack (consumes previously loaded sa/sb), then caller reloads
#define CSTEPA(PH, EMIT) { int a_;                                         \
    COMPUTE(sa, ndA, EMIT, a_) STORE(sA, ndA) PACK(w0A, a_, PH, bpwA) }
#define CSTEPB(PH, EMIT) { int a_;                                         \
    COMPUTE(sb, ndB, EMIT, a_) STORE(sB, ndB) PACK(w0B, a_, PH, bpwB) }
#define ILOADA LOADQ(sa, sA)
#define ILOADB LOADQ(sb, sB)

__global__ void __launch_bounds__(64, 1) viterbi_kernel(
    const float* __restrict__ P,          // [B, L, K]
    const float* __restrict__ Tm,         // [K, K]
    float* __restrict__ out)              // [B, L] float32
{
    extern __shared__ unsigned char dsm[];            // 4 * ROWBYTES
    __shared__ __align__(256) float dpbuf[2][2][2][32];
    __shared__ unsigned char fmap[2][2][NSEG][K];
    __shared__ unsigned char eseg[2][2][NSEG];

    const int wid  = threadIdx.x >> 5;
    const int lane = threadIdx.x & 31;
    const int j    = (lane < K) ? lane : 0;
    const unsigned laneoff = (unsigned)lane << 2;

    const int ww   = blockIdx.x * 2 + wid;
    const int rowA = g_ord[2 * ww];       // longer row
    const int rowB = g_ord[2 * ww + 1];   // shorter
    const int lenA = g_len[rowA];
    const int lenB = g_len[rowB];

    unsigned char* __restrict__ bpA = dsm + (wid * 2 + 0) * ROWBYTES;
    unsigned char* __restrict__ bpB = dsm + (wid * 2 + 1) * ROWBYTES;

    float Trow[K];
#pragma unroll
    for (int k = 0; k < K; ++k) Trow[k] = Tm[j * K + k];

    const float* PbA = P + (size_t)rowA * L * K;
    const float* PbB = P + (size_t)rowB * L * K;

    dpbuf[wid][0][0][lane] = (lane == START_ID) ? 0.0f : NEG;
    dpbuf[wid][0][1][lane] = NEG;
    dpbuf[wid][1][0][lane] = (lane == START_ID) ? 0.0f : NEG;
    dpbuf[wid][1][1][lane] = NEG;
    __syncwarp();

    unsigned sA = smem_u32(&dpbuf[wid][0][0][0]);
    unsigned sB = smem_u32(&dpbuf[wid][1][0][0]);

    float ndA = (j == START_ID && lane < K) ? 0.0f : NEG;
    float ndB = ndA;
    unsigned* bpwA = (unsigned*)bpA + lane;
    unsigned* bpwB = (unsigned*)bpB + lane;
    unsigned w0A = 0, w0B = 0;
    float sa[20], sb[20];

    float eA0 = __ldg(PbA + j + (size_t)min(0, lenA - 1) * K);
    float eA1 = __ldg(PbA + j + (size_t)min(1, lenA - 1) * K);
    float eA2 = __ldg(PbA + j + (size_t)min(2, lenA - 1) * K);
    float eA3 = __ldg(PbA + j + (size_t)min(3, lenA - 1) * K);
    float eB0 = __ldg(PbB + j + (size_t)min(0, lenB - 1) * K);
    float eB1 = __ldg(PbB + j + (size_t)min(1, lenB - 1) * K);
    float eB2 = __ldg(PbB + j + (size_t)min(2, lenB - 1) * K);
    float eB3 = __ldg(PbB + j + (size_t)min(3, lenB - 1) * K);

    // prologue loads: both rows' DP in flight before first consume
    ILOADA; ILOADB;

    int t = 0;
    // ---- phase 1: offset-interleaved groups (unguarded prefetch) ----
    {
        const float* epA = PbA + j + (size_t)4 * K;
        const float* epB = PbB + j + (size_t)4 * K;
        for (; t + 8 <= lenB; t += 4) {
            CSTEPA(0, eA0); ILOADA; eA0 = __ldg(epA + 0 * K);
            CSTEPB(0, eB0); ILOADB; eB0 = __ldg(epB + 0 * K);
            CSTEPA(1, eA1); ILOADA; eA1 = __ldg(epA + 1 * K);
            CSTEPB(1, eB1); ILOADB; eB1 = __ldg(epB + 1 * K);
            CSTEPA(2, eA2); ILOADA; eA2 = __ldg(epA + 2 * K);
            CSTEPB(2, eB2); ILOADB; eB2 = __ldg(epB + 2 * K);
            CSTEPA(3, eA3); ILOADA; eA3 = __ldg(epA + 3 * K);
            CSTEPB(3, eB3); ILOADB; eB3 = __ldg(epB + 3 * K);
            epA += 4 * K; epB += 4 * K;
        }
    }
    // ---- phase 1b: one clamped interleaved group ----
    if (t + 4 <= lenB) {
        CSTEPA(0, eA0); ILOADA;
        eA0 = __ldg(PbA + j + (size_t)min(t + 4, lenA - 1) * K);
        CSTEPB(0, eB0); ILOADB;
        eB0 = __ldg(PbB + j + (size_t)min(t + 4, lenB - 1) * K);
        CSTEPA(1, eA1); ILOADA;
        eA1 = __ldg(PbA + j + (size_t)min(t + 5, lenA - 1) * K);
        CSTEPB(1, eB1); ILOADB;
        eB1 = __ldg(PbB + j + (size_t)min(t + 5, lenB - 1) * K);
        CSTEPA(2, eA2); ILOADA;
        eA2 = __ldg(PbA + j + (size_t)min(t + 6, lenA - 1) * K);
        CSTEPB(2, eB2); ILOADB;
        eB2 = __ldg(PbB + j + (size_t)min(t + 6, lenB - 1) * K);
        CSTEPA(3, eA3); ILOADA;
        eA3 = __ldg(PbA + j + (size_t)min(t + 7, lenA - 1) * K);
        CSTEPB(3, eB3); ILOADB;
        eB3 = __ldg(PbB + j + (size_t)min(t + 7, lenB - 1) * K);
        t += 4;
    }
    // ---- phase 1c: partial group, rB in [0,3] ----
    {
        const int rB = lenB - t;
        const int rA4 = min(lenA - t, 4);
        if (rA4 > 0) { CSTEPA(0, eA0); ILOADA; }
        if (rB  > 0) { CSTEPB(0, eB0); ILOADB; }
        if (rA4 > 1) { CSTEPA(1, eA1); ILOADA; }
        if (rB  > 1) { CSTEPB(1, eB1); ILOADB; }
        if (rA4 > 2) { CSTEPA(2, eA2); ILOADA; }
        if (rB  > 2) { CSTEPB(2, eB2); ILOADB; }
        if (rA4 > 3) { CSTEPA(3, eA3); ILOADA; }
        if (rB > 0 && rB < 4 && lane < K) *bpwB = w0B;
        if (rA4 > 0 && rA4 < 4 && lane < K) *bpwA = w0A;
        t += rA4;
    }
    // ---- phase 2: A-only groups ----
    if (t + 8 <= lenA) {
        eA0 = __ldg(PbA + j + (size_t)(t + 0) * K);
        eA1 = __ldg(PbA + j + (size_t)(t + 1) * K);
        eA2 = __ldg(PbA + j + (size_t)(t + 2) * K);
        eA3 = __ldg(PbA + j + (size_t)(t + 3) * K);
        const float* epA = PbA + j + (size_t)(t + 4) * K;
        for (; t + 8 <= lenA; t += 4) {
            CSTEPA(0, eA0); ILOADA; eA0 = __ldg(epA + 0 * K);
            CSTEPA(1, eA1); ILOADA; eA1 = __ldg(epA + 1 * K);
            CSTEPA(2, eA2); ILOADA; eA2 = __ldg(epA + 2 * K);
            CSTEPA(3, eA3); ILOADA; eA3 = __ldg(epA + 3 * K);
            epA += 4 * K;
        }
    }
    // ---- phase 2 tail: r in [0,7] ----
    {
        const int r = lenA - t;
        if (r > 0) {
            eA0 = __ldg(PbA + j + (size_t)min(t + 0, lenA - 1) * K);
            eA1 = __ldg(PbA + j + (size_t)min(t + 1, lenA - 1) * K);
            eA2 = __ldg(PbA + j + (size_t)min(t + 2, lenA - 1) * K);
            eA3 = __ldg(PbA + j + (size_t)min(t + 3, lenA - 1) * K);
            CSTEPA(0, eA0); ILOADA;
            if (r > 1) { CSTEPA(1, eA1); ILOADA; }
            if (r > 2) { CSTEPA(2, eA2); ILOADA; }
            if (r > 3) { CSTEPA(3, eA3); ILOADA; }
            if (r > 4) { float ex = __ldg(PbA + j + (size_t)(t + 4) * K);
                         CSTEPA(0, ex); ILOADA; }
            if (r > 5) { float ex = __ldg(PbA + j + (size_t)(t + 5) * K);
                         CSTEPA(1, ex); ILOADA; }
            if (r > 6) { float ex = __ldg(PbA + j + (size_t)(t + 6) * K);
                         CSTEPA(2, ex); ILOADA; }
            if ((r & 3) != 0 && lane < K) *bpwA = w0A;
        }
    }
    __syncwarp();

    // ================= backtrack + output, per row =================
    for (int rsel = 0; rsel < 2; ++rsel) {
        const int brow = rsel ? rowB : rowA;
        const int blen = rsel ? lenB : lenA;
        const float bnd = rsel ? ndB : ndA;
        const unsigned char* __restrict__ bp = rsel ? bpB : bpA;

        const float fv = (lane < K) ? (bnd + Tm[PAD_ID * K + j]) : NEG;
        int last = 0;
        {
            float bestf = __shfl_sync(FULL, fv, 0);
#pragma unroll
            for (int k = 1; k < K; ++k) {
                const float vk = __shfl_sync(FULL, fv, k);
                if (vk > bestf) { bestf = vk; last = k; }
            }
        }

        float* ob = out + (size_t)brow * L;
        for (int tt = blen + lane; tt < L; tt += 32) ob[tt] = -1.0f;

        const int segw = (blen + NSEG - 1) / NSEG;
        const int nseg = (blen + segw - 1) / segw;

        int cur[CPL], tq[CPL], t0q[CPL];
#pragma unroll
        for (int q = 0; q < CPL; ++q) {
            const int cid = lane + 32 * q;
            if (cid < nseg * K) {
                const int i = cid / K, e = cid - i * K;
                const int t0 = i * segw;
                const int t1 = min(t0 + segw, blen);
                cur[q] = e; tq[q] = t1 - 1; t0q[q] = t0;
            } else { cur[q] = 0; tq[q] = 0; t0q[q] = 0; }
        }
        for (int p = 0; p < segw - 1; ++p) {
#pragma unroll
            for (int q = 0; q < CPL; ++q)
                if (tq[q] > t0q[q]) {
                    cur[q] = BPGET(bp, tq[q], cur[q]);
                    tq[q]--;
                }
        }
#pragma unroll
        for (int q = 0; q < CPL; ++q) {
            const int cid = lane + 32 * q;
            if (cid < nseg * K) {
                const int i = cid / K, e = cid - i * K;
                fmap[wid][rsel][i][e] = (unsigned char)cur[q];
            }
        }
        __syncwarp();

        if (lane == 0) {
            int e = last;
            eseg[wid][rsel][nseg - 1] = (unsigned char)e;
            for (int i = nseg - 1; i > 0; --i) {
                const int t0 = i * segw;
                const int pc = fmap[wid][rsel][i][e];
                e = BPGET(bp, t0, pc);
                eseg[wid][rsel][i - 1] = (unsigned char)e;
            }
        }
        __syncwarp();

        if (lane < nseg) {
            const int t0 = lane * segw;
            const int t1 = min(t0 + segw, blen);
            int c = eseg[wid][rsel][lane];
            ob[t1 - 1] = (float)c;
            for (int tt = t1 - 2; tt >= t0; --tt) {
                c = BPGET(bp, tt + 1, c);
                ob[tt] = (float)c;
            }
        }
        __syncwarp();
    }
}

extern "C" void kernel_launch(void* const* d_in, const int* in_sizes, int n_in,
                              void* d_out, int out_size) {
    const float* P = (const float*)d_in[0];
    const float* T = (const float*)d_in[1];
    const unsigned char* mask = (const unsigned char*)d_in[2];
    float* out = (float*)d_out;

    const int smem = 4 * ROWBYTES;  // 163840 B
    cudaFuncSetAttribute(viterbi_kernel,
                         cudaFuncAttributeMaxDynamicSharedMemorySize, smem);

    detect_kernel<<<1, 256>>>(mask);
    length_kernel<<<128, 128>>>(mask);
    sort_kernel<<<1, 512>>>();
    viterbi_kernel<<<B / 4, 64, smem>>>(P, T, out);
}

// round 16
// speedup vs baseline: 1.6022x; 1.4884x over previous
#include <cuda_runtime.h>

#define K 19
#define L 2048
#define B 512
#define START_ID 17
#define PAD_ID 18
#define NEG -1000.0f
#define NW 4
#define NSEG 16
#define CPL 10
#define FULL 0xffffffffu
#define ROWBYTES (L / 8 * 160)  // packed bp: [L/8 groups][20 lanes][8 bytes]

__device__ int g_elt4;

__global__ void detect_kernel(const unsigned char* __restrict__ m) {
    __shared__ int found;
    if (threadIdx.x == 0) found = 0;
    __syncthreads();
    int f = 0;
    for (int i = threadIdx.x * 4 + 1; i < 65536; i += blockDim.x * 4)
        f |= m[i];
    if (f) found = 1;
    __syncthreads();
    if (threadIdx.x == 0) g_elt4 = found ? 0 : 1;
}

__device__ __forceinline__ int BPGET(const unsigned char* bp, int t, int c) {
    return bp[((t >> 3) * 160) + (c << 3) + (t & 7)];
}

__device__ __forceinline__ unsigned smem_u32(const void* p) {
    unsigned a;
    asm("{ .reg .u64 t; cvta.to.shared.u64 t, %1; cvt.u32.u64 %0, t; }"
        : "=r"(a) : "l"(p));
    return a;
}

// load next step's DP vector (issued right after the STS; lands in the
// shadow of the mask phase that follows in program order)
#define LOADQ(S, SRC)                                                      \
    asm volatile("ld.shared.v4.f32 {%0,%1,%2,%3}, [%4];"                   \
        : "=f"(S[0]), "=f"(S[1]), "=f"(S[2]), "=f"(S[3])                   \
        : "r"(SRC) : "memory");                                            \
    asm volatile("ld.shared.v4.f32 {%0,%1,%2,%3}, [%4];"                   \
        : "=f"(S[4]), "=f"(S[5]), "=f"(S[6]), "=f"(S[7])                   \
        : "r"((SRC) + 16) : "memory");                                     \
    asm volatile("ld.shared.v4.f32 {%0,%1,%2,%3}, [%4];"                   \
        : "=f"(S[8]), "=f"(S[9]), "=f"(S[10]), "=f"(S[11])                 \
        : "r"((SRC) + 32) : "memory");                                     \
    asm volatile("ld.shared.v4.f32 {%0,%1,%2,%3}, [%4];"                   \
        : "=f"(S[12]), "=f"(S[13]), "=f"(S[14]), "=f"(S[15])               \
        : "r"((SRC) + 48) : "memory");                                     \
    asm volatile("ld.shared.v4.f32 {%0,%1,%2,%3}, [%4];"                   \
        : "=f"(S[16]), "=f"(S[17]), "=f"(S[18]), "=f"(S[19])               \
        : "r"((SRC) + 64) : "memory");

// value phase: adds in place, pure fmaxf tree, emit add, STS. No argmax.
#define CSTEP(S, BV, EMIT, DST) {                                          \
    S[0]+=Trow[0];   S[1]+=Trow[1];   S[2]+=Trow[2];   S[3]+=Trow[3];      \
    S[4]+=Trow[4];   S[5]+=Trow[5];   S[6]+=Trow[6];   S[7]+=Trow[7];      \
    S[8]+=Trow[8];   S[9]+=Trow[9];   S[10]+=Trow[10]; S[11]+=Trow[11];    \
    S[12]+=Trow[12]; S[13]+=Trow[13]; S[14]+=Trow[14]; S[15]+=Trow[15];    \
    S[16]+=Trow[16]; S[17]+=Trow[17]; S[18]+=Trow[18];                     \
    float m0=fmaxf(S[0],S[1]),  m1=fmaxf(S[2],S[3]),  m2=fmaxf(S[4],S[5]); \
    float m3=fmaxf(S[6],S[7]),  m4=fmaxf(S[8],S[9]),  m5=fmaxf(S[10],S[11]);\
    float m6=fmaxf(S[12],S[13]),m7=fmaxf(S[14],S[15]),m8=fmaxf(S[16],S[17]);\
    m0=fmaxf(m0,m1); m2=fmaxf(m2,m3); m4=fmaxf(m4,m5); m6=fmaxf(m6,m7);    \
    m8=fmaxf(m8,S[18]);                                                    \
    m0=fmaxf(m0,m2); m4=fmaxf(m4,m6);                                      \
    m0=fmaxf(m0,m4); BV=fmaxf(m0,m8);                                      \
    nd = BV + (EMIT);                                                      \
    asm volatile("st.shared.f32 [%0], %1;"                                 \
        :: "r"((DST) + laneoff), "f"(nd) : "memory");                      \
}

// mask phase (in the LDS shadow): first-occurrence argmax + byte pack
#define BSTEP(S, BV, PH) {                                                 \
    unsigned mb = 0u;                                                      \
    _Pragma("unroll")                                                      \
    for (int k2 = 0; k2 < K; ++k2)                                         \
        mb |= (S[k2] == (BV)) ? (1u << k2) : 0u;                           \
    unsigned argb = (unsigned)(__ffs(mb) - 1);                             \
    if ((PH) == 0)      w0 = argb;                                         \
    else if ((PH) < 4)  w0 |= argb << (8 * (PH));                          \
    else if ((PH) == 4) w1 = argb;                                         \
    else                w1 |= argb << (8 * ((PH) - 4));                    \
    if ((PH) == 7) {                                                       \
        if (lane < K)                                                      \
            *bpq = (unsigned long long)w0 |                                \
                   ((unsigned long long)w1 << 32);                         \
        bpq += 20;                                                         \
    }                                                                      \
}

// full step: compute+store (buffer S), load next into SN, mask in shadow
#define FSTEP(S, SN, BV, EMIT, DST, PH)                                    \
    CSTEP(S, BV, EMIT, DST)                                                \
    LOADQ(SN, DST)                                                         \
    BSTEP(S, BV, PH)

__global__ void __launch_bounds__(NW * 32, 1) viterbi_kernel(
    const float* __restrict__ P,          // [B, L, K]
    const float* __restrict__ Tm,         // [K, K]: T[j*K+k], prev k -> cur j
    const unsigned char* __restrict__ mask,
    float* __restrict__ out)              // [B, L] float32
{
    extern __shared__ unsigned char dsm[];            // NW * ROWBYTES
    __shared__ __align__(16) float dpbuf[NW][2][32];
    __shared__ unsigned char fmap[NW][NSEG][K];
    __shared__ unsigned char eseg[NW][NSEG];

    const int wid  = threadIdx.x >> 5;
    const int lane = threadIdx.x & 31;
    const int b    = blockIdx.x * NW + wid;
    const int j    = (lane < K) ? lane : 0;
    const unsigned laneoff = (unsigned)lane << 2;

    unsigned char* __restrict__ bp = dsm + wid * ROWBYTES;

    // ---- sequence length ----
    int len = 0;
    if (g_elt4) {
        const unsigned int* m = (const unsigned int*)mask + (size_t)b * L;
        for (int i = lane; i < L; i += 32) len += (m[i] != 0u);
    } else {
        const unsigned char* m = mask + (size_t)b * L;
        for (int i = lane; i < L; i += 32) len += (m[i] != 0);
    }
#pragma unroll
    for (int o = 16; o; o >>= 1) len += __shfl_xor_sync(FULL, len, o);

    float Trow[K];
#pragma unroll
    for (int k = 0; k < K; ++k) Trow[k] = Tm[j * K + k];

    const float* Pb = P + (size_t)b * L * K;

    dpbuf[wid][0][lane] = (lane == START_ID) ? 0.0f : NEG;
    dpbuf[wid][1][lane] = NEG;
    __syncwarp();

    const unsigned dpA = smem_u32(&dpbuf[wid][0][0]);
    const unsigned dpB = dpA + 128;

    float nd = (j == START_ID && lane < K) ? 0.0f : NEG;
    unsigned long long* bpq = (unsigned long long*)bp + lane;
    unsigned w0 = 0, w1 = 0;
    float s0[20], s1[20], b0, b1;

    if (len >= 24) {
        const float* ep = Pb + j;
        float e0 = __ldg(ep + 0 * K), e1 = __ldg(ep + 1 * K);
        float e2 = __ldg(ep + 2 * K), e3 = __ldg(ep + 3 * K);
        float e4 = __ldg(ep + 4 * K), e5 = __ldg(ep + 5 * K);
        float e6 = __ldg(ep + 6 * K), e7 = __ldg(ep + 7 * K);
        ep += 8 * K;

        LOADQ(s0, dpA);   // prologue load

        // prologue group: steps 0..7
        FSTEP(s0, s1, b0, e0, dpB, 0); e0 = __ldg(ep + 0 * K);
        FSTEP(s1, s0, b1, e1, dpA, 1); e1 = __ldg(ep + 1 * K);
        FSTEP(s0, s1, b0, e2, dpB, 2); e2 = __ldg(ep + 2 * K);
        FSTEP(s1, s0, b1, e3, dpA, 3); e3 = __ldg(ep + 3 * K);
        FSTEP(s0, s1, b0, e4, dpB, 4); e4 = __ldg(ep + 4 * K);
        FSTEP(s1, s0, b1, e5, dpA, 5); e5 = __ldg(ep + 5 * K);
        FSTEP(s0, s1, b0, e6, dpB, 6); e6 = __ldg(ep + 6 * K);
        FSTEP(s1, s0, b1, e7, dpA, 7); e7 = __ldg(ep + 7 * K);
        ep += 8 * K;

        int t = 8;
        for (; t + 16 <= len; t += 8) {
            FSTEP(s0, s1, b0, e0, dpB, 0); e0 = __ldg(ep + 0 * K);
            FSTEP(s1, s0, b1, e1, dpA, 1); e1 = __ldg(ep + 1 * K);
            FSTEP(s0, s1, b0, e2, dpB, 2); e2 = __ldg(ep + 2 * K);
            FSTEP(s1, s0, b1, e3, dpA, 3); e3 = __ldg(ep + 3 * K);
            FSTEP(s0, s1, b0, e4, dpB, 4); e4 = __ldg(ep + 4 * K);
            FSTEP(s1, s0, b1, e5, dpA, 5); e5 = __ldg(ep + 5 * K);
            FSTEP(s0, s1, b0, e6, dpB, 6); e6 = __ldg(ep + 6 * K);
            FSTEP(s1, s0, b1, e7, dpA, 7); e7 = __ldg(ep + 7 * K);
            ep += 8 * K;
        }

        // epilogue: r = len - t in [8, 15]
        const int r = len - t;
        if (r > 0) FSTEP(s0, s1, b0, e0, dpB, 0);
        if (r > 1) FSTEP(s1, s0, b1, e1, dpA, 1);
        if (r > 2) FSTEP(s0, s1, b0, e2, dpB, 2);
        if (r > 3) FSTEP(s1, s0, b1, e3, dpA, 3);
        if (r > 4) FSTEP(s0, s1, b0, e4, dpB, 4);
        if (r > 5) FSTEP(s1, s0, b1, e5, dpA, 5);
        if (r > 6) FSTEP(s0, s1, b0, e6, dpB, 6);
        if (r > 7) FSTEP(s1, s0, b1, e7, dpA, 7);
        if (r > 8)  { float ex = __ldg(Pb + j + (t + 8) * K);
                      FSTEP(s0, s1, b0, ex, dpB, 0); }
        if (r > 9)  { float ex = __ldg(Pb + j + (t + 9) * K);
                      FSTEP(s1, s0, b1, ex, dpA, 1); }
        if (r > 10) { float ex = __ldg(Pb + j + (t + 10) * K);
                      FSTEP(s0, s1, b0, ex, dpB, 2); }
        if (r > 11) { float ex = __ldg(Pb + j + (t + 11) * K);
                      FSTEP(s1, s0, b1, ex, dpA, 3); }
        if (r > 12) { float ex = __ldg(Pb + j + (t + 12) * K);
                      FSTEP(s0, s1, b0, ex, dpB, 4); }
        if (r > 13) { float ex = __ldg(Pb + j + (t + 13) * K);
                      FSTEP(s1, s0, b1, ex, dpA, 5); }
        if (r > 14) { float ex = __ldg(Pb + j + (t + 14) * K);
                      FSTEP(s0, s1, b0, ex, dpB, 6); }
        if (r > 8 && lane < K)
            *bpq = (unsigned long long)w0 | ((unsigned long long)w1 << 32);
    } else {
        // ---- slow path: len < 24 (barrier version, rare) ----
        float* cb = dpbuf[wid][0];
        float* nb = dpbuf[wid][1];
        for (int s2 = 0; s2 < len; ++s2) {
            const float emit = __ldg(Pb + j + s2 * K);
            float d[20];
            *(float4*)&d[0]  = *(const float4*)&cb[0];
            *(float4*)&d[4]  = *(const float4*)&cb[4];
            *(float4*)&d[8]  = *(const float4*)&cb[8];
            *(float4*)&d[12] = *(const float4*)&cb[12];
            *(float4*)&d[16] = *(const float4*)&cb[16];
#pragma unroll
            for (int k = 0; k < K; ++k) s0[k] = d[k] + Trow[k];
            float best = s0[0];
#pragma unroll
            for (int k = 1; k < K; ++k) best = fmaxf(best, s0[k]);
            unsigned mb = 0u;
#pragma unroll
            for (int k = 0; k < K; ++k) mb |= (s0[k] == best) ? (1u << k) : 0u;
            nd = best + emit;
            nb[lane] = nd;
            __syncwarp();
            float* tmp = cb; cb = nb; nb = tmp;
            if (lane < K)
                bp[((s2 >> 3) * 160) + (lane << 3) + (s2 & 7)] =
                    (unsigned char)(__ffs(mb) - 1);
        }
    }
    __syncwarp();

    // ---- final transition into PAD, first-occurrence argmax ----
    const float fv = (lane < K) ? (nd + Tm[PAD_ID * K + j]) : NEG;
    int last = 0;
    {
        float bestf = __shfl_sync(FULL, fv, 0);
#pragma unroll
        for (int k = 1; k < K; ++k) {
            const float vk = __shfl_sync(FULL, fv, k);
            if (vk > bestf) { bestf = vk; last = k; }
        }
    }

    float* ob = out + (size_t)b * L;
    for (int tt = len + lane; tt < L; tt += 32) ob[tt] = -1.0f;

    // ---- backtrack, warp-local two-pass ----
    const int segw = (len + NSEG - 1) / NSEG;
    const int nseg = (len + segw - 1) / segw;

    int cur[CPL], tq[CPL], t0q[CPL];
#pragma unroll
    for (int q = 0; q < CPL; ++q) {
        const int cid = lane + 32 * q;
        if (cid < nseg * K) {
            const int i = cid / K, e = cid - i * K;
            const int t0 = i * segw;
            const int t1 = min(t0 + segw, len);
            cur[q] = e; tq[q] = t1 - 1; t0q[q] = t0;
        } else { cur[q] = 0; tq[q] = 0; t0q[q] = 0; }
    }
    for (int p = 0; p < segw - 1; ++p) {
#pragma unroll
        for (int q = 0; q < CPL; ++q)
            if (tq[q] > t0q[q]) {
                cur[q] = BPGET(bp, tq[q], cur[q]);
                tq[q]--;
            }
    }
#pragma unroll
    for (int q = 0; q < CPL; ++q) {
        const int cid = lane + 32 * q;
        if (cid < nseg * K) {
            const int i = cid / K, e = cid - i * K;
            fmap[wid][i][e] = (unsigned char)cur[q];
        }
    }
    __syncwarp();

    if (lane == 0) {
        int e = last;
        eseg[wid][nseg - 1] = (unsigned char)e;
        for (int i = nseg - 1; i > 0; --i) {
            const int t0 = i * segw;
            const int pc = fmap[wid][i][e];
            e = BPGET(bp, t0, pc);
            eseg[wid][i - 1] = (unsigned char)e;
        }
    }
    __syncwarp();

    if (lane < nseg) {
        const int t0 = lane * segw;
        const int t1 = min(t0 + segw, len);
        int c = eseg[wid][lane];
        ob[t1 - 1] = (float)c;
        for (int tt = t1 - 2; tt >= t0; --tt) {
            c = BPGET(bp, tt + 1, c);
            ob[tt] = (float)c;
        }
    }
}

extern "C" void kernel_launch(void* const* d_in, const int* in_sizes, int n_in,
                              void* d_out, int out_size) {
    const float* P = (const float*)d_in[0];
    const float* T = (const float*)d_in[1];
    const unsigned char* mask = (const unsigned char*)d_in[2];
    float* out = (float*)d_out;

    const int smem = NW * ROWBYTES;  // 163840 B
    cudaFuncSetAttribute(viterbi_kernel,
                         cudaFuncAttributeMaxDynamicSharedMemorySize, smem);

    detect_kernel<<<1, 256>>>(mask);
    viterbi_kernel<<<B / NW, NW * 32, smem>>>(P, T, mask, out);
}

// round 17
// speedup vs baseline: 1.6882x; 1.0537x over previous
#include <cuda_runtime.h>

#define K 19
#define L 2048
#define B 512
#define START_ID 17
#define PAD_ID 18
#define NEG -1000.0f
#define NW 4
#define NSEG 16
#define CPL 10
#define FULL 0xffffffffu
#define ROWBYTES (L / 8 * 160)  // packed bp: [L/8 groups][20 lanes][8 bytes]

__device__ int g_elt4;

__global__ void detect_kernel(const unsigned char* __restrict__ m) {
    __shared__ int found;
    if (threadIdx.x == 0) found = 0;
    __syncthreads();
    int f = 0;
    for (int i = threadIdx.x * 4 + 1; i < 65536; i += blockDim.x * 4)
        f |= m[i];
    if (f) found = 1;
    __syncthreads();
    if (threadIdx.x == 0) g_elt4 = found ? 0 : 1;
}

__device__ __forceinline__ int BPGET(const unsigned char* bp, int t, int c) {
    return bp[((t >> 3) * 160) + (c << 3) + (t & 7)];
}

__device__ __forceinline__ unsigned smem_u32(const void* p) {
    unsigned a;
    asm("{ .reg .u64 t; cvta.to.shared.u64 t, %1; cvt.u32.u64 %0, t; }"
        : "=r"(a) : "l"(p));
    return a;
}

#define LOADQ(S, SRC)                                                      \
    asm volatile("ld.shared.v4.f32 {%0,%1,%2,%3}, [%4];"                   \
        : "=f"(S[0]), "=f"(S[1]), "=f"(S[2]), "=f"(S[3])                   \
        : "r"(SRC) : "memory");                                            \
    asm volatile("ld.shared.v4.f32 {%0,%1,%2,%3}, [%4];"                   \
        : "=f"(S[4]), "=f"(S[5]), "=f"(S[6]), "=f"(S[7])                   \
        : "r"((SRC) + 16) : "memory");                                     \
    asm volatile("ld.shared.v4.f32 {%0,%1,%2,%3}, [%4];"                   \
        : "=f"(S[8]), "=f"(S[9]), "=f"(S[10]), "=f"(S[11])                 \
        : "r"((SRC) + 32) : "memory");                                     \
    asm volatile("ld.shared.v4.f32 {%0,%1,%2,%3}, [%4];"                   \
        : "=f"(S[12]), "=f"(S[13]), "=f"(S[14]), "=f"(S[15])               \
        : "r"((SRC) + 48) : "memory");                                     \
    asm volatile("ld.shared.v4.f32 {%0,%1,%2,%3}, [%4];"                   \
        : "=f"(S[16]), "=f"(S[17]), "=f"(S[18]), "=f"(S[19])               \
        : "r"((SRC) + 64) : "memory");

// value phase: adds in place, pure fmaxf tree, emit add, STS.
#define CSTEP(S, BV, EMIT, DST) {                                          \
    S[0]+=Trow[0];   S[1]+=Trow[1];   S[2]+=Trow[2];   S[3]+=Trow[3];      \
    S[4]+=Trow[4];   S[5]+=Trow[5];   S[6]+=Trow[6];   S[7]+=Trow[7];      \
    S[8]+=Trow[8];   S[9]+=Trow[9];   S[10]+=Trow[10]; S[11]+=Trow[11];    \
    S[12]+=Trow[12]; S[13]+=Trow[13]; S[14]+=Trow[14]; S[15]+=Trow[15];    \
    S[16]+=Trow[16]; S[17]+=Trow[17]; S[18]+=Trow[18];                     \
    float m0=fmaxf(S[0],S[1]),  m1=fmaxf(S[2],S[3]),  m2=fmaxf(S[4],S[5]); \
    float m3=fmaxf(S[6],S[7]),  m4=fmaxf(S[8],S[9]),  m5=fmaxf(S[10],S[11]);\
    float m6=fmaxf(S[12],S[13]),m7=fmaxf(S[14],S[15]),m8=fmaxf(S[16],S[17]);\
    m0=fmaxf(m0,m1); m2=fmaxf(m2,m3); m4=fmaxf(m4,m5); m6=fmaxf(m6,m7);    \
    m8=fmaxf(m8,S[18]);                                                    \
    m0=fmaxf(m0,m2); m4=fmaxf(m4,m6);                                      \
    m0=fmaxf(m0,m4); BV=fmaxf(m0,m8);                                      \
    nd = BV + (EMIT);                                                      \
    asm volatile("st.shared.f32 [%0], %1;"                                 \
        :: "r"((DST) + laneoff), "f"(nd) : "memory");                      \
}

// mask half A: bits 0..9 (filler between STS and LDS; lets store drain)
#define MASKA(S, BV) {                                                     \
    mb_ = 0u;                                                              \
    _Pragma("unroll")                                                      \
    for (int k2 = 0; k2 < 10; ++k2)                                        \
        mb_ |= (S[k2] == (BV)) ? (1u << k2) : 0u;                          \
}

// mask half B: bits 10..18 + ffs + pack (fills the LDS latency shadow)
#define MASKB(S, BV, PH) {                                                 \
    _Pragma("unroll")                                                      \
    for (int k2 = 10; k2 < K; ++k2)                                        \
        mb_ |= (S[k2] == (BV)) ? (1u << k2) : 0u;                          \
    unsigned argb = (unsigned)(__ffs(mb_) - 1);                            \
    if ((PH) == 0)      w0 = argb;                                         \
    else if ((PH) < 4)  w0 |= argb << (8 * (PH));                          \
    else if ((PH) == 4) w1 = argb;                                         \
    else                w1 |= argb << (8 * ((PH) - 4));                    \
    if ((PH) == 7) {                                                       \
        if (lane < K)                                                      \
            *bpq = (unsigned long long)w0 |                                \
                   ((unsigned long long)w1 << 32);                         \
        bpq += 20;                                                         \
    }                                                                      \
}

// full step: value+STS, maskA (store drains), LDS next, maskB (LDS shadow)
#define FSTEP(S, SN, BV, EMIT, DST, PH) {                                  \
    unsigned mb_;                                                          \
    CSTEP(S, BV, EMIT, DST)                                                \
    MASKA(S, BV)                                                           \
    LOADQ(SN, DST)                                                         \
    MASKB(S, BV, PH)                                                       \
}

__global__ void __launch_bounds__(NW * 32, 1) viterbi_kernel(
    const float* __restrict__ P,          // [B, L, K]
    const float* __restrict__ Tm,         // [K, K]: T[j*K+k], prev k -> cur j
    const unsigned char* __restrict__ mask,
    float* __restrict__ out)              // [B, L] float32
{
    extern __shared__ unsigned char dsm[];            // NW * ROWBYTES
    __shared__ __align__(16) float dpbuf[NW][2][32];
    __shared__ unsigned char fmap[NW][NSEG][K];
    __shared__ unsigned char eseg[NW][NSEG];

    const int wid  = threadIdx.x >> 5;
    const int lane = threadIdx.x & 31;
    const int b    = blockIdx.x * NW + wid;
    const int j    = (lane < K) ? lane : 0;
    const unsigned laneoff = (unsigned)lane << 2;

    unsigned char* __restrict__ bp = dsm + wid * ROWBYTES;

    // ---- sequence length ----
    int len = 0;
    if (g_elt4) {
        const unsigned int* m = (const unsigned int*)mask + (size_t)b * L;
        for (int i = lane; i < L; i += 32) len += (m[i] != 0u);
    } else {
        const unsigned char* m = mask + (size_t)b * L;
        for (int i = lane; i < L; i += 32) len += (m[i] != 0);
    }
#pragma unroll
    for (int o = 16; o; o >>= 1) len += __shfl_xor_sync(FULL, len, o);

    float Trow[K];
#pragma unroll
    for (int k = 0; k < K; ++k) Trow[k] = Tm[j * K + k];

    const float* Pb = P + (size_t)b * L * K;

    dpbuf[wid][0][lane] = (lane == START_ID) ? 0.0f : NEG;
    dpbuf[wid][1][lane] = NEG;
    __syncwarp();

    const unsigned dpA = smem_u32(&dpbuf[wid][0][0]);
    const unsigned dpB = dpA + 128;

    float nd = (j == START_ID && lane < K) ? 0.0f : NEG;
    unsigned long long* bpq = (unsigned long long*)bp + lane;
    unsigned w0 = 0, w1 = 0;
    float s0[20], s1[20], b0, b1;

    if (len >= 24) {
        const float* ep = Pb + j;
        float e0 = __ldg(ep + 0 * K), e1 = __ldg(ep + 1 * K);
        float e2 = __ldg(ep + 2 * K), e3 = __ldg(ep + 3 * K);
        float e4 = __ldg(ep + 4 * K), e5 = __ldg(ep + 5 * K);
        float e6 = __ldg(ep + 6 * K), e7 = __ldg(ep + 7 * K);
        ep += 8 * K;

        LOADQ(s0, dpA);   // prologue load

        // prologue group: steps 0..7
        FSTEP(s0, s1, b0, e0, dpB, 0); e0 = __ldg(ep + 0 * K);
        FSTEP(s1, s0, b1, e1, dpA, 1); e1 = __ldg(ep + 1 * K);
        FSTEP(s0, s1, b0, e2, dpB, 2); e2 = __ldg(ep + 2 * K);
        FSTEP(s1, s0, b1, e3, dpA, 3); e3 = __ldg(ep + 3 * K);
        FSTEP(s0, s1, b0, e4, dpB, 4); e4 = __ldg(ep + 4 * K);
        FSTEP(s1, s0, b1, e5, dpA, 5); e5 = __ldg(ep + 5 * K);
        FSTEP(s0, s1, b0, e6, dpB, 6); e6 = __ldg(ep + 6 * K);
        FSTEP(s1, s0, b1, e7, dpA, 7); e7 = __ldg(ep + 7 * K);
        ep += 8 * K;

        int t = 8;
        for (; t + 16 <= len; t += 8) {
            FSTEP(s0, s1, b0, e0, dpB, 0); e0 = __ldg(ep + 0 * K);
            FSTEP(s1, s0, b1, e1, dpA, 1); e1 = __ldg(ep + 1 * K);
            FSTEP(s0, s1, b0, e2, dpB, 2); e2 = __ldg(ep + 2 * K);
            FSTEP(s1, s0, b1, e3, dpA, 3); e3 = __ldg(ep + 3 * K);
            FSTEP(s0, s1, b0, e4, dpB, 4); e4 = __ldg(ep + 4 * K);
            FSTEP(s1, s0, b1, e5, dpA, 5); e5 = __ldg(ep + 5 * K);
            FSTEP(s0, s1, b0, e6, dpB, 6); e6 = __ldg(ep + 6 * K);
            FSTEP(s1, s0, b1, e7, dpA, 7); e7 = __ldg(ep + 7 * K);
            ep += 8 * K;
        }

        // epilogue: r = len - t in [8, 15]
        const int r = len - t;
        if (r > 0) FSTEP(s0, s1, b0, e0, dpB, 0);
        if (r > 1) FSTEP(s1, s0, b1, e1, dpA, 1);
        if (r > 2) FSTEP(s0, s1, b0, e2, dpB, 2);
        if (r > 3) FSTEP(s1, s0, b1, e3, dpA, 3);
        if (r > 4) FSTEP(s0, s1, b0, e4, dpB, 4);
        if (r > 5) FSTEP(s1, s0, b1, e5, dpA, 5);
        if (r > 6) FSTEP(s0, s1, b0, e6, dpB, 6);
        if (r > 7) FSTEP(s1, s0, b1, e7, dpA, 7);
        if (r > 8)  { float ex = __ldg(Pb + j + (t + 8) * K);
                      FSTEP(s0, s1, b0, ex, dpB, 0); }
        if (r > 9)  { float ex = __ldg(Pb + j + (t + 9) * K);
                      FSTEP(s1, s0, b1, ex, dpA, 1); }
        if (r > 10) { float ex = __ldg(Pb + j + (t + 10) * K);
                      FSTEP(s0, s1, b0, ex, dpB, 2); }
        if (r > 11) { float ex = __ldg(Pb + j + (t + 11) * K);
                      FSTEP(s1, s0, b1, ex, dpA, 3); }
        if (r > 12) { float ex = __ldg(Pb + j + (t + 12) * K);
                      FSTEP(s0, s1, b0, ex, dpB, 4); }
        if (r > 13) { float ex = __ldg(Pb + j + (t + 13) * K);
                      FSTEP(s1, s0, b1, ex, dpA, 5); }
        if (r > 14) { float ex = __ldg(Pb + j + (t + 14) * K);
                      FSTEP(s0, s1, b0, ex, dpB, 6); }
        if (r > 8 && lane < K)
            *bpq = (unsigned long long)w0 | ((unsigned long long)w1 << 32);
    } else {
        // ---- slow path: len < 24 (barrier version, rare) ----
        float* cb = dpbuf[wid][0];
        float* nb = dpbuf[wid][1];
        for (int s2 = 0; s2 < len; ++s2) {
            const float emit = __ldg(Pb + j + s2 * K);
            float d[20];
            *(float4*)&d[0]  = *(const float4*)&cb[0];
            *(float4*)&d[4]  = *(const float4*)&cb[4];
            *(float4*)&d[8]  = *(const float4*)&cb[8];
            *(float4*)&d[12] = *(const float4*)&cb[12];
            *(float4*)&d[16] = *(const float4*)&cb[16];
#pragma unroll
            for (int k = 0; k < K; ++k) s0[k] = d[k] + Trow[k];
            float best = s0[0];
#pragma unroll
            for (int k = 1; k < K; ++k) best = fmaxf(best, s0[k]);
            unsigned mb = 0u;
#pragma unroll
            for (int k = 0; k < K; ++k) mb |= (s0[k] == best) ? (1u << k) : 0u;
            nd = best + emit;
            nb[lane] = nd;
            __syncwarp();
            float* tmp = cb; cb = nb; nb = tmp;
            if (lane < K)
                bp[((s2 >> 3) * 160) + (lane << 3) + (s2 & 7)] =
                    (unsigned char)(__ffs(mb) - 1);
        }
    }
    __syncwarp();

    // ---- final transition into PAD, first-occurrence argmax ----
    const float fv = (lane < K) ? (nd + Tm[PAD_ID * K + j]) : NEG;
    int last = 0;
    {
        float bestf = __shfl_sync(FULL, fv, 0);
#pragma unroll
        for (int k = 1; k < K; ++k) {
            const float vk = __shfl_sync(FULL, fv, k);
            if (vk > bestf) { bestf = vk; last = k; }
        }
    }

    float* ob = out + (size_t)b * L;
    for (int tt = len + lane; tt < L; tt += 32) ob[tt] = -1.0f;

    // ---- backtrack, warp-local two-pass ----
    const int segw = (len + NSEG - 1) / NSEG;
    const int nseg = (len + segw - 1) / segw;

    int cur[CPL], tq[CPL], t0q[CPL];
#pragma unroll
    for (int q = 0; q < CPL; ++q) {
        const int cid = lane + 32 * q;
        if (cid < nseg * K) {
            const int i = cid / K, e = cid - i * K;
            const int t0 = i * segw;
            const int t1 = min(t0 + segw, len);
            cur[q] = e; tq[q] = t1 - 1; t0q[q] = t0;
        } else { cur[q] = 0; tq[q] = 0; t0q[q] = 0; }
    }
    for (int p = 0; p < segw - 1; ++p) {
#pragma unroll
        for (int q = 0; q < CPL; ++q)
            if (tq[q] > t0q[q]) {
                cur[q] = BPGET(bp, tq[q], cur[q]);
                tq[q]--;
            }
    }
#pragma unroll
    for (int q = 0; q < CPL; ++q) {
        const int cid = lane + 32 * q;
        if (cid < nseg * K) {
            const int i = cid / K, e = cid - i * K;
            fmap[wid][i][e] = (unsigned char)cur[q];
        }
    }
    __syncwarp();

    if (lane == 0) {
        int e = last;
        eseg[wid][nseg - 1] = (unsigned char)e;
        for (int i = nseg - 1; i > 0; --i) {
            const int t0 = i * segw;
            const int pc = fmap[wid][i][e];
            e = BPGET(bp, t0, pc);
            eseg[wid][i - 1] = (unsigned char)e;
        }
    }
    __syncwarp();

    if (lane < nseg) {
        const int t0 = lane * segw;
        const int t1 = min(t0 + segw, len);
        int c = eseg[wid][lane];
        ob[t1 - 1] = (float)c;
        for (int tt = t1 - 2; tt >= t0; --tt) {
            c = BPGET(bp, tt + 1, c);
            ob[tt] = (float)c;
        }
    }
}

extern "C" void kernel_launch(void* const* d_in, const int* in_sizes, int n_in,
                              void* d_out, int out_size) {
    const float* P = (const float*)d_in[0];
    const float* T = (const float*)d_in[1];
    const unsigned char* mask = (const unsigned char*)d_in[2];
    float* out = (float*)d_out;

    const int smem = NW * ROWBYTES;  // 163840 B
    cudaFuncSetAttribute(viterbi_kernel,
                         cudaFuncAttributeMaxDynamicSharedMemorySize, smem);

    detect_kernel<<<1, 256>>>(mask);
    viterbi_kernel<<<B / NW, NW * 32, smem>>>(P, T, mask, out);
}